// round 6
// baseline (speedup 1.0000x reference)
#include <cuda_runtime.h>
#include <cuda_fp16.h>
#include <cstdint>

// ---------------- problem constants ----------------
constexpr int U = 100000;
constexpr int I = 50000;
constexpr int D = 64;        // embed dim
constexpr int E = 2000000;   // bipartite edges
constexpr int N = U + I;     // 150000
constexpr int E2 = 2 * E;    // symmetric (self loops handled analytically)
constexpr int NH = D / 2;    // half2 per row = 32
constexpr int NBLK = 147;    // scan blocks of 1024
constexpr float EPS = 1e-12f;
constexpr float FXS  = 1099511627776.0f;      // 2^40
constexpr float FXSI = 1.0f / 1099511627776.0f;

// ---------------- device scratch (static, no allocs) ----------------
__device__ unsigned long long g_cnt64[N];     // [63:48] count, [47:0] fixed-point weight sum
__device__ float   g_dinv[N];
__device__ int     g_cnt [N];
__device__ int     g_off [N];
__device__ int     g_cur [N];
__device__ int     g_bsum[256];
__device__ int4    g_edge4[E2 / 2];           // pairs of {src, bitcast(nrm)}
__device__ __half2 g_xl[4][(size_t)N * NH];   // layer outputs x0..x3 (fp16)

// ---------------- K1: zero cnt64 + user embeddings ----------------
__global__ void k1_init_user(const float* __restrict__ user_w, int nz) {
    if (blockIdx.x < nz) {
        int i = blockIdx.x * blockDim.x + threadIdx.x;
        if (i < N) g_cnt64[i] = 0ull;
        return;
    }
    int gw = (blockIdx.x - nz) * 8 + (threadIdx.x >> 5);
    int l  = threadIdx.x & 31;
    if (gw >= U) return;
    float2 v = ((const float2*)(user_w + (size_t)gw * D))[l];
    float ss = v.x * v.x + v.y * v.y;
    #pragma unroll
    for (int o = 16; o; o >>= 1) ss += __shfl_xor_sync(0xffffffffu, ss, o);
    float inv = 1.0f / fmaxf(sqrtf(ss), EPS);
    g_xl[0][(size_t)gw * NH + l] = __floats2half2_rn(v.x * inv, v.y * inv);
}

// ---------------- K2: packed degree atomics ----------------
__global__ void k_deg(const float* __restrict__ ew,
                      const int* __restrict__ u_idx,
                      const int* __restrict__ i_idx) {
    int e = blockIdx.x * blockDim.x + threadIdx.x;
    if (e >= E) return;
    float w = fmaxf(ew[e], 1e-6f);
    unsigned long long enc = (1ull << 48) | (unsigned long long)(w * FXS);
    atomicAdd(&g_cnt64[u_idx[e]],     enc);
    atomicAdd(&g_cnt64[U + i_idx[e]], enc);
}

// ---------------- K2b: item embeddings (gather + proj GEMV + l2norm) ----------------
__global__ void k_item(const float* __restrict__ audio,
                       const float* __restrict__ artw,
                       const float* __restrict__ albw,
                       const float* __restrict__ W,     // [64][128] row-major
                       const float* __restrict__ bvec,  // [64]
                       const int*   __restrict__ aid,
                       const int*   __restrict__ bid) {
    __shared__ float2 Wt[128 * 32];    // Wt[k][l] = (W[2l][k], W[2l+1][k])
    __shared__ float  bs[64];
    __shared__ float  feat[8][128];
    int t = threadIdx.x;
    for (int i = t; i < 128 * 32; i += blockDim.x) {
        int k = i >> 5, l = i & 31;
        Wt[i] = make_float2(W[(2 * l) * 128 + k], W[(2 * l + 1) * 128 + k]);
    }
    if (t < 64) bs[t] = bvec[t];
    __syncthreads();

    int wid = t >> 5, l = t & 31;
    int gw = blockIdx.x * 8 + wid;
    int nw = gridDim.x * 8;
    for (int item = gw; item < I; item += nw) {
        int a  = aid[item];
        int b2 = bid[item];
        #pragma unroll
        for (int j = 0; j < 4; j++) {
            int k = l + j * 32;
            float f;
            if (k < 64) f = audio[(size_t)item * 64 + k];
            else        f = artw[(size_t)a * 64 + (k - 64)] + albw[(size_t)b2 * 64 + (k - 64)];
            feat[wid][k] = f;
        }
        __syncwarp();
        float y0 = bs[2 * l], y1 = bs[2 * l + 1];
        #pragma unroll 8
        for (int k = 0; k < 128; k++) {
            float f = feat[wid][k];
            float2 w2 = Wt[k * 32 + l];
            y0 += f * w2.x;
            y1 += f * w2.y;
        }
        float ss = y0 * y0 + y1 * y1;
        #pragma unroll
        for (int o = 16; o; o >>= 1) ss += __shfl_xor_sync(0xffffffffu, ss, o);
        float inv = 1.0f / fmaxf(sqrtf(ss), EPS);
        g_xl[0][(size_t)(U + item) * NH + l] = __floats2half2_rn(y0 * inv, y1 * inv);
        __syncwarp();
    }
}

// ---------------- K3: decode cnt/dinv + block-local exclusive scan ----------------
__global__ void k_scan1() {
    __shared__ int sh[1024];
    int t = threadIdx.x;
    int i = blockIdx.x * 1024 + t;
    int v = 0;
    if (i < N) {
        unsigned long long c = g_cnt64[i];
        v = (int)(c >> 48);
        float deg = (float)(c & 0xFFFFFFFFFFFFull) * FXSI + 1.0f;  // +1 self loop
        g_dinv[i] = rsqrtf(deg);
        g_cnt[i]  = v;
    }
    sh[t] = v;
    __syncthreads();
    #pragma unroll
    for (int off = 1; off < 1024; off <<= 1) {
        int add = (t >= off) ? sh[t - off] : 0;
        __syncthreads();
        sh[t] += add;
        __syncthreads();
    }
    if (i < N) g_off[i] = sh[t] - v;            // exclusive within block
    if (t == 1023) g_bsum[blockIdx.x] = sh[1023];
}

// ---------------- K4: inline bsum scan + global offsets ----------------
__global__ void k_scan3() {
    __shared__ int sb[256];
    int t = threadIdx.x;
    if (t < 256) sb[t] = (t < NBLK) ? g_bsum[t] : 0;
    __syncthreads();
    #pragma unroll
    for (int off = 1; off < 256; off <<= 1) {
        int add = (t < 256 && t >= off) ? sb[t - off] : 0;
        __syncthreads();
        if (t < 256) sb[t] += add;
        __syncthreads();
    }
    int excl = (blockIdx.x > 0) ? sb[blockIdx.x - 1] : 0;   // inclusive of previous blocks
    int i = blockIdx.x * 1024 + t;
    if (i < N) {
        int o = g_off[i] + excl;
        g_off[i] = o;
        g_cur[i] = o;
    }
}

// ---------------- K5: CSR fill ----------------
__global__ void k_fill(const float* __restrict__ ew,
                       const int* __restrict__ u_idx,
                       const int* __restrict__ i_idx) {
    int e = blockIdx.x * blockDim.x + threadIdx.x;
    if (e >= E) return;
    int u  = u_idx[e];
    int it = U + i_idx[e];
    float w   = fmaxf(ew[e], 1e-6f);
    float nrm = g_dinv[u] * w * g_dinv[it];
    int nb = __float_as_int(nrm);
    int2* edges = (int2*)g_edge4;
    int p  = atomicAdd(&g_cur[u], 1);
    edges[p] = make_int2(it, nb);
    int q  = atomicAdd(&g_cur[it], 1);
    edges[q] = make_int2(u, nb);
}

// ---------------- SpMM helper ----------------
__device__ __forceinline__ void addE(float4& a, float n, uint2 v) {
    __half2 h0 = *(__half2*)&v.x, h1 = *(__half2*)&v.y;
    float2 f0 = __half22float2(h0), f1 = __half22float2(h1);
    a.x = fmaf(n, f0.x, a.x); a.y = fmaf(n, f0.y, a.y);
    a.z = fmaf(n, f1.x, a.z); a.w = fmaf(n, f1.y, a.w);
}

// ---------------- K6-8: SpMM, one warp per dest node, half-warp per edge ----------------
__global__ void k_spmm(int lin, int lout) {
    int gw = (blockIdx.x * blockDim.x + threadIdx.x) >> 5;
    if (gw >= N) return;
    int l   = threadIdx.x & 31;
    int sub = l >> 4;             // which half-warp
    int sl  = l & 15;             // lane within half: uint2 index into 128B row
    const uint2* __restrict__ xin = (const uint2*)g_xl[lin];

    int   beg = g_off[gw];
    int   end = beg + g_cnt[gw];
    float di  = g_dinv[gw];

    float4 acc = make_float4(0.f, 0.f, 0.f, 0.f);

    // self loop (count once: half 0 only)
    {
        uint2 v = xin[(size_t)gw * 16 + sl];
        if (sub == 0) addE(acc, di * di, v);
    }

    const int2* edges = (const int2*)g_edge4;
    int e = beg;
    if ((e & 1) && e < end) {                     // align to pair boundary
        int2 ed = edges[e];
        uint2 v = xin[(size_t)ed.x * 16 + sl];
        if (sub == 0) addE(acc, __int_as_float(ed.y), v);
        e++;
    }
    int pend = e + ((end - e) & ~1);              // pair-aligned end

    for (; e + 8 <= pend; e += 8) {
        int4 p0 = g_edge4[(e >> 1) + 0];
        int4 p1 = g_edge4[(e >> 1) + 1];
        int4 p2 = g_edge4[(e >> 1) + 2];
        int4 p3 = g_edge4[(e >> 1) + 3];
        int s0 = sub ? p0.z : p0.x;  float n0 = __int_as_float(sub ? p0.w : p0.y);
        int s1 = sub ? p1.z : p1.x;  float n1 = __int_as_float(sub ? p1.w : p1.y);
        int s2 = sub ? p2.z : p2.x;  float n2 = __int_as_float(sub ? p2.w : p2.y);
        int s3 = sub ? p3.z : p3.x;  float n3 = __int_as_float(sub ? p3.w : p3.y);
        uint2 v0 = xin[(size_t)s0 * 16 + sl];
        uint2 v1 = xin[(size_t)s1 * 16 + sl];
        uint2 v2 = xin[(size_t)s2 * 16 + sl];
        uint2 v3 = xin[(size_t)s3 * 16 + sl];
        addE(acc, n0, v0);
        addE(acc, n1, v1);
        addE(acc, n2, v2);
        addE(acc, n3, v3);
    }
    for (; e + 2 <= pend; e += 2) {
        int4 p = g_edge4[e >> 1];
        int s = sub ? p.z : p.x;  float n = __int_as_float(sub ? p.w : p.y);
        uint2 v = xin[(size_t)s * 16 + sl];
        addE(acc, n, v);
    }
    if (pend < end) {                             // single trailing edge
        int2 ed = edges[pend];
        uint2 v = xin[(size_t)ed.x * 16 + sl];
        if (sub == 0) addE(acc, __int_as_float(ed.y), v);
    }

    // combine the two half-warps
    acc.x += __shfl_xor_sync(0xffffffffu, acc.x, 16);
    acc.y += __shfl_xor_sync(0xffffffffu, acc.y, 16);
    acc.z += __shfl_xor_sync(0xffffffffu, acc.z, 16);
    acc.w += __shfl_xor_sync(0xffffffffu, acc.w, 16);

    if (sub == 0) {
        __half2 h0 = __floats2half2_rn(acc.x, acc.y);
        __half2 h1 = __floats2half2_rn(acc.z, acc.w);
        uint2 o;
        o.x = *(unsigned*)&h0;
        o.y = *(unsigned*)&h1;
        ((uint2*)g_xl[lout])[(size_t)gw * 16 + sl] = o;
    }
}

// ---------------- K9: out = l2norm((x0+x1+x2+x3) / 4) ----------------
__global__ void k_final(float* __restrict__ out) {
    int gw = (blockIdx.x * blockDim.x + threadIdx.x) >> 5;
    int l  = threadIdx.x & 31;
    if (gw >= N) return;
    size_t idx = (size_t)gw * NH + l;
    float2 a0 = __half22float2(g_xl[0][idx]);
    float2 a1 = __half22float2(g_xl[1][idx]);
    float2 a2 = __half22float2(g_xl[2][idx]);
    float2 a3 = __half22float2(g_xl[3][idx]);
    float ax = (a0.x + a1.x + a2.x + a3.x) * 0.25f;
    float ay = (a0.y + a1.y + a2.y + a3.y) * 0.25f;
    float ss = ax * ax + ay * ay;
    #pragma unroll
    for (int o = 16; o; o >>= 1) ss += __shfl_xor_sync(0xffffffffu, ss, o);
    float inv = 1.0f / fmaxf(sqrtf(ss), EPS);
    ((float2*)(out + (size_t)gw * D))[l] = make_float2(ax * inv, ay * inv);
}

// ---------------- launcher ----------------
extern "C" void kernel_launch(void* const* d_in, const int* in_sizes, int n_in,
                              void* d_out, int out_size) {
    const float* user_w     = (const float*)d_in[0];
    const float* item_audio = (const float*)d_in[1];
    const float* artist_w   = (const float*)d_in[2];
    const float* album_w    = (const float*)d_in[3];
    const float* proj_W     = (const float*)d_in[4];
    const float* proj_b     = (const float*)d_in[5];
    const float* edge_w     = (const float*)d_in[6];
    const int*   u_idx      = (const int*)d_in[7];
    const int*   i_idx      = (const int*)d_in[8];
    const int*   artist_ids = (const int*)d_in[9];
    const int*   album_ids  = (const int*)d_in[10];
    float* out = (float*)d_out;

    const int TB = 256;
    int nz = (N + TB - 1) / TB;                 // zero blocks
    int gE = (E + TB - 1) / TB;

    k1_init_user<<<nz + (U + 7) / 8, TB>>>(user_w, nz);
    k_deg <<<gE, TB>>>(edge_w, u_idx, i_idx);
    k_item<<<1184, TB>>>(item_audio, artist_w, album_w, proj_W, proj_b,
                         artist_ids, album_ids);
    k_scan1<<<NBLK, 1024>>>();
    k_scan3<<<NBLK, 1024>>>();
    k_fill <<<gE, TB>>>(edge_w, u_idx, i_idx);

    int gW = (N * 32 + TB - 1) / TB;
    k_spmm <<<gW, TB>>>(0, 1);
    k_spmm <<<gW, TB>>>(1, 2);
    k_spmm <<<gW, TB>>>(2, 3);
    k_final<<<gW, TB>>>(out);
}

// round 9
// speedup vs baseline: 1.1435x; 1.1435x over previous
#include <cuda_runtime.h>
#include <cuda_fp16.h>
#include <cstdint>

// ---------------- problem constants ----------------
constexpr int U = 100000;
constexpr int I = 50000;
constexpr int D = 64;        // embed dim
constexpr int E = 2000000;   // bipartite edges
constexpr int N = U + I;     // 150000
constexpr int E2 = 2 * E;    // symmetric (self loops handled analytically)
constexpr int NH = D / 2;    // half2 per row = 32
constexpr int NBLK = 147;    // scan blocks of 1024
constexpr float EPS = 1e-12f;
constexpr float FXS  = 1099511627776.0f;      // 2^40
constexpr float FXSI = 1.0f / 1099511627776.0f;

// ---------------- device scratch (static, no allocs) ----------------
__device__ unsigned long long g_cnt64[N];     // [63:48] count, [47:0] fixed-point weight sum
__device__ float   g_dinv[N];
__device__ int     g_cnt [N];
__device__ int     g_off [N];
__device__ int     g_cur [N];
__device__ int     g_bsum[256];
__device__ int4    g_edge4[E2 / 2];           // pairs of {src, bitcast(nrm)}
__device__ __half2 g_xl[3][(size_t)N * NH];   // layer outputs x0..x2 (fp16); x3 fused

// ---------------- K1: zero cnt64 + user embeddings ----------------
__global__ void k1_init_user(const float* __restrict__ user_w, int nz) {
    if (blockIdx.x < nz) {
        int i = blockIdx.x * blockDim.x + threadIdx.x;
        if (i < N) g_cnt64[i] = 0ull;
        return;
    }
    int gw = (blockIdx.x - nz) * 8 + (threadIdx.x >> 5);
    int l  = threadIdx.x & 31;
    if (gw >= U) return;
    float2 v = ((const float2*)(user_w + (size_t)gw * D))[l];
    float ss = v.x * v.x + v.y * v.y;
    #pragma unroll
    for (int o = 16; o; o >>= 1) ss += __shfl_xor_sync(0xffffffffu, ss, o);
    float inv = 1.0f / fmaxf(sqrtf(ss), EPS);
    g_xl[0][(size_t)gw * NH + l] = __floats2half2_rn(v.x * inv, v.y * inv);
}

// ---------------- K2: packed degree atomics ----------------
__global__ void k_deg(const float* __restrict__ ew,
                      const int* __restrict__ u_idx,
                      const int* __restrict__ i_idx) {
    int e = blockIdx.x * blockDim.x + threadIdx.x;
    if (e >= E) return;
    float w = fmaxf(ew[e], 1e-6f);
    unsigned long long enc = (1ull << 48) | (unsigned long long)(w * FXS);
    atomicAdd(&g_cnt64[u_idx[e]],     enc);
    atomicAdd(&g_cnt64[U + i_idx[e]], enc);
}

// ---------------- K2b: item embeddings (gather + proj GEMV + l2norm) ----------------
__global__ void k_item(const float* __restrict__ audio,
                       const float* __restrict__ artw,
                       const float* __restrict__ albw,
                       const float* __restrict__ W,     // [64][128] row-major
                       const float* __restrict__ bvec,  // [64]
                       const int*   __restrict__ aid,
                       const int*   __restrict__ bid) {
    __shared__ float2 Wt[128 * 32];    // Wt[k][l] = (W[2l][k], W[2l+1][k])
    __shared__ float  bs[64];
    __shared__ float  feat[8][128];
    int t = threadIdx.x;
    for (int i = t; i < 128 * 32; i += blockDim.x) {
        int k = i >> 5, l = i & 31;
        Wt[i] = make_float2(W[(2 * l) * 128 + k], W[(2 * l + 1) * 128 + k]);
    }
    if (t < 64) bs[t] = bvec[t];
    __syncthreads();

    int wid = t >> 5, l = t & 31;
    int gw = blockIdx.x * 8 + wid;
    int nw = gridDim.x * 8;
    for (int item = gw; item < I; item += nw) {
        int a  = aid[item];
        int b2 = bid[item];
        #pragma unroll
        for (int j = 0; j < 4; j++) {
            int k = l + j * 32;
            float f;
            if (k < 64) f = audio[(size_t)item * 64 + k];
            else        f = artw[(size_t)a * 64 + (k - 64)] + albw[(size_t)b2 * 64 + (k - 64)];
            feat[wid][k] = f;
        }
        __syncwarp();
        float y0 = bs[2 * l], y1 = bs[2 * l + 1];
        #pragma unroll 8
        for (int k = 0; k < 128; k++) {
            float f = feat[wid][k];
            float2 w2 = Wt[k * 32 + l];
            y0 += f * w2.x;
            y1 += f * w2.y;
        }
        float ss = y0 * y0 + y1 * y1;
        #pragma unroll
        for (int o = 16; o; o >>= 1) ss += __shfl_xor_sync(0xffffffffu, ss, o);
        float inv = 1.0f / fmaxf(sqrtf(ss), EPS);
        g_xl[0][(size_t)(U + item) * NH + l] = __floats2half2_rn(y0 * inv, y1 * inv);
        __syncwarp();
    }
}

// ---------------- K3: decode cnt/dinv + block-local exclusive scan ----------------
__global__ void k_scan1() {
    __shared__ int sh[1024];
    int t = threadIdx.x;
    int i = blockIdx.x * 1024 + t;
    int v = 0;
    if (i < N) {
        unsigned long long c = g_cnt64[i];
        v = (int)(c >> 48);
        float deg = (float)(c & 0xFFFFFFFFFFFFull) * FXSI + 1.0f;  // +1 self loop
        g_dinv[i] = rsqrtf(deg);
        g_cnt[i]  = v;
    }
    sh[t] = v;
    __syncthreads();
    #pragma unroll
    for (int off = 1; off < 1024; off <<= 1) {
        int add = (t >= off) ? sh[t - off] : 0;
        __syncthreads();
        sh[t] += add;
        __syncthreads();
    }
    if (i < N) g_off[i] = sh[t] - v;            // exclusive within block
    if (t == 1023) g_bsum[blockIdx.x] = sh[1023];
}

// ---------------- K4: inline bsum scan + global offsets ----------------
__global__ void k_scan3() {
    __shared__ int sb[256];
    int t = threadIdx.x;
    if (t < 256) sb[t] = (t < NBLK) ? g_bsum[t] : 0;
    __syncthreads();
    #pragma unroll
    for (int off = 1; off < 256; off <<= 1) {
        int add = (t < 256 && t >= off) ? sb[t - off] : 0;
        __syncthreads();
        if (t < 256) sb[t] += add;
        __syncthreads();
    }
    int excl = (blockIdx.x > 0) ? sb[blockIdx.x - 1] : 0;
    int i = blockIdx.x * 1024 + t;
    if (i < N) {
        int o = g_off[i] + excl;
        g_off[i] = o;
        g_cur[i] = o;
    }
}

// ---------------- K5: CSR fill ----------------
__global__ void k_fill(const float* __restrict__ ew,
                       const int* __restrict__ u_idx,
                       const int* __restrict__ i_idx) {
    int e = blockIdx.x * blockDim.x + threadIdx.x;
    if (e >= E) return;
    int u  = u_idx[e];
    int it = U + i_idx[e];
    float w   = fmaxf(ew[e], 1e-6f);
    float nrm = g_dinv[u] * w * g_dinv[it];
    int nb = __float_as_int(nrm);
    int2* edges = (int2*)g_edge4;
    int p  = atomicAdd(&g_cur[u], 1);
    edges[p] = make_int2(it, nb);
    int q  = atomicAdd(&g_cur[it], 1);
    edges[q] = make_int2(u, nb);
}

// ---------------- SpMM helper: full-warp gather accumulate ----------------
__device__ __forceinline__ void addH(float& ax, float& ay, float n, __half2 h) {
    float2 f = __half22float2(h);
    ax = fmaf(n, f.x, ax);
    ay = fmaf(n, f.y, ay);
}

// ---------------- K6-8: SpMM, one warp per dest node, full-warp per edge ----------------
// lout < 3: write fp16 layer buffer. lout == 3: fuse final l2norm((x0+x1+x2+x3)/4) -> out.
__global__ void k_spmm(int lin, int lout, float* __restrict__ out) {
    int gw = (blockIdx.x * blockDim.x + threadIdx.x) >> 5;
    if (gw >= N) return;
    int l = threadIdx.x & 31;
    const __half2* __restrict__ xin = g_xl[lin];
    size_t idx = (size_t)gw * NH + l;

    int   beg = g_off[gw];
    int   end = beg + g_cnt[gw];
    float di  = g_dinv[gw];

    float2 s = __half22float2(xin[idx]);
    float ax = s.x * (di * di), ay = s.y * (di * di);   // self loop

    const int2* edges = (const int2*)g_edge4;
    int e = beg;
    if ((e & 1) && e < end) {                      // align to pair boundary
        int2 ed = edges[e];
        addH(ax, ay, __int_as_float(ed.y), xin[(size_t)ed.x * NH + l]);
        e++;
    }
    int pend = e + ((end - e) & ~1);               // pair-aligned end

    for (; e + 8 <= pend; e += 8) {                // 4 int4 loads = 8 edges, 8 gathers in flight
        int4 p0 = g_edge4[(e >> 1) + 0];
        int4 p1 = g_edge4[(e >> 1) + 1];
        int4 p2 = g_edge4[(e >> 1) + 2];
        int4 p3 = g_edge4[(e >> 1) + 3];
        __half2 v0 = xin[(size_t)p0.x * NH + l];
        __half2 v1 = xin[(size_t)p0.z * NH + l];
        __half2 v2 = xin[(size_t)p1.x * NH + l];
        __half2 v3 = xin[(size_t)p1.z * NH + l];
        __half2 v4 = xin[(size_t)p2.x * NH + l];
        __half2 v5 = xin[(size_t)p2.z * NH + l];
        __half2 v6 = xin[(size_t)p3.x * NH + l];
        __half2 v7 = xin[(size_t)p3.z * NH + l];
        addH(ax, ay, __int_as_float(p0.y), v0);
        addH(ax, ay, __int_as_float(p0.w), v1);
        addH(ax, ay, __int_as_float(p1.y), v2);
        addH(ax, ay, __int_as_float(p1.w), v3);
        addH(ax, ay, __int_as_float(p2.y), v4);
        addH(ax, ay, __int_as_float(p2.w), v5);
        addH(ax, ay, __int_as_float(p3.y), v6);
        addH(ax, ay, __int_as_float(p3.w), v7);
    }
    for (; e + 2 <= pend; e += 2) {
        int4 p = g_edge4[e >> 1];
        __half2 va = xin[(size_t)p.x * NH + l];
        __half2 vb = xin[(size_t)p.z * NH + l];
        addH(ax, ay, __int_as_float(p.y), va);
        addH(ax, ay, __int_as_float(p.w), vb);
    }
    if (pend < end) {                              // single trailing edge
        int2 ed = edges[pend];
        addH(ax, ay, __int_as_float(ed.y), xin[(size_t)ed.x * NH + l]);
    }

    if (lout < 3) {
        g_xl[lout][idx] = __floats2half2_rn(ax, ay);
    } else {
        // fused final: acc = x0 + x1 + x2 + x3(this); l2norm(acc/4)
        float2 a0 = __half22float2(g_xl[0][idx]);
        float2 a1 = __half22float2(g_xl[1][idx]);
        float2 a2 = __half22float2(g_xl[2][idx]);
        float fx = (ax + a0.x + a1.x + a2.x) * 0.25f;
        float fy = (ay + a0.y + a1.y + a2.y) * 0.25f;
        float ss = fx * fx + fy * fy;
        #pragma unroll
        for (int o = 16; o; o >>= 1) ss += __shfl_xor_sync(0xffffffffu, ss, o);
        float inv = 1.0f / fmaxf(sqrtf(ss), EPS);
        ((float2*)(out + (size_t)gw * D))[l] = make_float2(fx * inv, fy * inv);
    }
}

// ---------------- launcher ----------------
extern "C" void kernel_launch(void* const* d_in, const int* in_sizes, int n_in,
                              void* d_out, int out_size) {
    const float* user_w     = (const float*)d_in[0];
    const float* item_audio = (const float*)d_in[1];
    const float* artist_w   = (const float*)d_in[2];
    const float* album_w    = (const float*)d_in[3];
    const float* proj_W     = (const float*)d_in[4];
    const float* proj_b     = (const float*)d_in[5];
    const float* edge_w     = (const float*)d_in[6];
    const int*   u_idx      = (const int*)d_in[7];
    const int*   i_idx      = (const int*)d_in[8];
    const int*   artist_ids = (const int*)d_in[9];
    const int*   album_ids  = (const int*)d_in[10];
    float* out = (float*)d_out;

    const int TB = 256;
    int nz = (N + TB - 1) / TB;                 // zero blocks
    int gE = (E + TB - 1) / TB;

    k1_init_user<<<nz + (U + 7) / 8, TB>>>(user_w, nz);
    k_deg <<<gE, TB>>>(edge_w, u_idx, i_idx);
    k_item<<<1184, TB>>>(item_audio, artist_w, album_w, proj_W, proj_b,
                         artist_ids, album_ids);
    k_scan1<<<NBLK, 1024>>>();
    k_scan3<<<NBLK, 1024>>>();
    k_fill <<<gE, TB>>>(edge_w, u_idx, i_idx);

    int gW = (N * 32 + TB - 1) / TB;
    k_spmm <<<gW, TB>>>(0, 1, out);
    k_spmm <<<gW, TB>>>(1, 2, out);
    k_spmm <<<gW, TB>>>(2, 3, out);   // fused final layer + l2norm
}

// round 12
// speedup vs baseline: 1.2298x; 1.0754x over previous
#include <cuda_runtime.h>
#include <cuda_fp16.h>
#include <cstdint>

// ---------------- problem constants ----------------
constexpr int U = 100000;
constexpr int I = 50000;
constexpr int D = 64;        // embed dim
constexpr int E = 2000000;   // bipartite edges
constexpr int N = U + I;     // 150000
constexpr int E2 = 2 * E;    // symmetric (self loops handled analytically)
constexpr int NH = D / 2;    // half2 per row = 32
constexpr int NBLK = 147;    // scan blocks of 1024
constexpr float EPS = 1e-12f;
constexpr float FXS  = 1099511627776.0f;      // 2^40
constexpr float FXSI = 1.0f / 1099511627776.0f;

// k_item GEMM tile config
constexpr int TM = 64;                 // items per block tile
constexpr int APAD = 132;              // 128 + 4 (16B-aligned rows, conflict-free)
constexpr int BPAD = 68;               // 64 + 4

// ---------------- device scratch (static, no allocs) ----------------
__device__ unsigned long long g_cnt64[N];     // [63:48] count, [47:0] fixed-point weight sum
__device__ float   g_dinv[N];
__device__ int     g_cnt [N];
__device__ int     g_off [N];
__device__ int     g_cur [N];
__device__ int     g_bsum[256];
__device__ int4    g_edge4[E2 / 2];           // pairs of {src, bitcast(nrm)}
__device__ __half2 g_xl[3][(size_t)N * NH];   // layer outputs x0..x2 (fp16); x3 fused

// ---------------- K1: zero cnt64 + user embeddings ----------------
__global__ void k1_init_user(const float* __restrict__ user_w, int nz) {
    if (blockIdx.x < nz) {
        int i = blockIdx.x * blockDim.x + threadIdx.x;
        if (i < N) g_cnt64[i] = 0ull;
        return;
    }
    int gw = (blockIdx.x - nz) * 8 + (threadIdx.x >> 5);
    int l  = threadIdx.x & 31;
    if (gw >= U) return;
    float2 v = ((const float2*)(user_w + (size_t)gw * D))[l];
    float ss = v.x * v.x + v.y * v.y;
    #pragma unroll
    for (int o = 16; o; o >>= 1) ss += __shfl_xor_sync(0xffffffffu, ss, o);
    float inv = 1.0f / fmaxf(sqrtf(ss), EPS);
    g_xl[0][(size_t)gw * NH + l] = __floats2half2_rn(v.x * inv, v.y * inv);
}

// ---------------- K2: packed degree atomics ----------------
__global__ void k_deg(const float* __restrict__ ew,
                      const int* __restrict__ u_idx,
                      const int* __restrict__ i_idx) {
    int e = blockIdx.x * blockDim.x + threadIdx.x;
    if (e >= E) return;
    float w = fmaxf(ew[e], 1e-6f);
    unsigned long long enc = (1ull << 48) | (unsigned long long)(w * FXS);
    atomicAdd(&g_cnt64[u_idx[e]],     enc);
    atomicAdd(&g_cnt64[U + i_idx[e]], enc);
}

// ---------------- K2b: item embeddings — tiled register-blocked SGEMM ----------------
// C[64 items][64 dims] = feat[64][128] @ Wt[128][64] + b, then row l2norm -> fp16.
// 256 threads: (tx 0..15, ty 0..15), each computes 4 items x 4 dims.
__global__ void k_item(const float* __restrict__ audio,
                       const float* __restrict__ artw,
                       const float* __restrict__ albw,
                       const float* __restrict__ W,     // [64][128] row-major
                       const float* __restrict__ bvec,  // [64]
                       const int*   __restrict__ aid,
                       const int*   __restrict__ bid) {
    extern __shared__ float sm[];
    float* As = sm;                        // [TM][APAD]
    float* Bs = sm + TM * APAD;            // [128][BPAD]
    float* bs = Bs + 128 * BPAD;           // [64]

    int t  = threadIdx.x;
    int tx = t & 15, ty = t >> 4;
    int i0 = blockIdx.x * TM;

    // stage B: Wt[k][d] = W[d][k]  (coalesced gmem read, transposed smem write)
    for (int e = t; e < 128 * 64; e += 256) {
        int k = e & 127, d = e >> 7;
        Bs[k * BPAD + d] = W[d * 128 + k];
    }
    if (t < 64) bs[t] = bvec[t];

    // stage A: feat rows (audio | artist+album), zero OOB rows
    for (int e = t; e < TM * 128; e += 256) {
        int item = e >> 7, k = e & 127;
        int r = i0 + item;
        float v = 0.0f;
        if (r < I) {
            if (k < 64) v = audio[(size_t)r * 64 + k];
            else {
                int a  = aid[r];
                int b2 = bid[r];
                v = artw[(size_t)a * 64 + (k - 64)] + albw[(size_t)b2 * 64 + (k - 64)];
            }
        }
        As[item * APAD + k] = v;
    }
    __syncthreads();

    float acc[4][4];
    #pragma unroll
    for (int i = 0; i < 4; i++)
        #pragma unroll
        for (int j = 0; j < 4; j++) acc[i][j] = 0.0f;

    const float* arow0 = As + (4 * ty + 0) * APAD;
    const float* arow1 = As + (4 * ty + 1) * APAD;
    const float* arow2 = As + (4 * ty + 2) * APAD;
    const float* arow3 = As + (4 * ty + 3) * APAD;

    #pragma unroll 2
    for (int k0 = 0; k0 < 128; k0 += 4) {
        float4 a0 = *(const float4*)(arow0 + k0);
        float4 a1 = *(const float4*)(arow1 + k0);
        float4 a2 = *(const float4*)(arow2 + k0);
        float4 a3 = *(const float4*)(arow3 + k0);
        #pragma unroll
        for (int kk = 0; kk < 4; kk++) {
            float4 b4 = *(const float4*)(Bs + (k0 + kk) * BPAD + 4 * tx);
            float av0 = (&a0.x)[kk], av1 = (&a1.x)[kk], av2 = (&a2.x)[kk], av3 = (&a3.x)[kk];
            acc[0][0] = fmaf(av0, b4.x, acc[0][0]); acc[0][1] = fmaf(av0, b4.y, acc[0][1]);
            acc[0][2] = fmaf(av0, b4.z, acc[0][2]); acc[0][3] = fmaf(av0, b4.w, acc[0][3]);
            acc[1][0] = fmaf(av1, b4.x, acc[1][0]); acc[1][1] = fmaf(av1, b4.y, acc[1][1]);
            acc[1][2] = fmaf(av1, b4.z, acc[1][2]); acc[1][3] = fmaf(av1, b4.w, acc[1][3]);
            acc[2][0] = fmaf(av2, b4.x, acc[2][0]); acc[2][1] = fmaf(av2, b4.y, acc[2][1]);
            acc[2][2] = fmaf(av2, b4.z, acc[2][2]); acc[2][3] = fmaf(av2, b4.w, acc[2][3]);
            acc[3][0] = fmaf(av3, b4.x, acc[3][0]); acc[3][1] = fmaf(av3, b4.y, acc[3][1]);
            acc[3][2] = fmaf(av3, b4.z, acc[3][2]); acc[3][3] = fmaf(av3, b4.w, acc[3][3]);
        }
    }

    // bias + per-item l2norm (reduce squares across the 16 tx lanes of this ty half)
    #pragma unroll
    for (int i = 0; i < 4; i++) {
        #pragma unroll
        for (int j = 0; j < 4; j++) acc[i][j] += bs[4 * tx + j];
        float ss = acc[i][0] * acc[i][0] + acc[i][1] * acc[i][1]
                 + acc[i][2] * acc[i][2] + acc[i][3] * acc[i][3];
        #pragma unroll
        for (int o = 8; o; o >>= 1) ss += __shfl_xor_sync(0xffffffffu, ss, o);
        float inv = 1.0f / fmaxf(sqrtf(ss), EPS);
        int r = i0 + 4 * ty + i;
        if (r < I) {
            __half2 h0 = __floats2half2_rn(acc[i][0] * inv, acc[i][1] * inv);
            __half2 h1 = __floats2half2_rn(acc[i][2] * inv, acc[i][3] * inv);
            uint2 o2;
            o2.x = *(unsigned*)&h0;
            o2.y = *(unsigned*)&h1;
            ((uint2*)g_xl[0])[(size_t)(U + r) * 16 + tx] = o2;
        }
    }
}

// ---------------- K3: decode cnt/dinv + block-local exclusive scan ----------------
__global__ void k_scan1() {
    __shared__ int sh[1024];
    int t = threadIdx.x;
    int i = blockIdx.x * 1024 + t;
    int v = 0;
    if (i < N) {
        unsigned long long c = g_cnt64[i];
        v = (int)(c >> 48);
        float deg = (float)(c & 0xFFFFFFFFFFFFull) * FXSI + 1.0f;  // +1 self loop
        g_dinv[i] = rsqrtf(deg);
        g_cnt[i]  = v;
    }
    sh[t] = v;
    __syncthreads();
    #pragma unroll
    for (int off = 1; off < 1024; off <<= 1) {
        int add = (t >= off) ? sh[t - off] : 0;
        __syncthreads();
        sh[t] += add;
        __syncthreads();
    }
    if (i < N) g_off[i] = sh[t] - v;            // exclusive within block
    if (t == 1023) g_bsum[blockIdx.x] = sh[1023];
}

// ---------------- K4: inline bsum scan + global offsets ----------------
__global__ void k_scan3() {
    __shared__ int sb[256];
    int t = threadIdx.x;
    if (t < 256) sb[t] = (t < NBLK) ? g_bsum[t] : 0;
    __syncthreads();
    #pragma unroll
    for (int off = 1; off < 256; off <<= 1) {
        int add = (t < 256 && t >= off) ? sb[t - off] : 0;
        __syncthreads();
        if (t < 256) sb[t] += add;
        __syncthreads();
    }
    int excl = (blockIdx.x > 0) ? sb[blockIdx.x - 1] : 0;
    int i = blockIdx.x * 1024 + t;
    if (i < N) {
        int o = g_off[i] + excl;
        g_off[i] = o;
        g_cur[i] = o;
    }
}

// ---------------- K5: CSR fill ----------------
__global__ void k_fill(const float* __restrict__ ew,
                       const int* __restrict__ u_idx,
                       const int* __restrict__ i_idx) {
    int e = blockIdx.x * blockDim.x + threadIdx.x;
    if (e >= E) return;
    int u  = u_idx[e];
    int it = U + i_idx[e];
    float w   = fmaxf(ew[e], 1e-6f);
    float nrm = g_dinv[u] * w * g_dinv[it];
    int nb = __float_as_int(nrm);
    int2* edges = (int2*)g_edge4;
    int p  = atomicAdd(&g_cur[u], 1);
    edges[p] = make_int2(it, nb);
    int q  = atomicAdd(&g_cur[it], 1);
    edges[q] = make_int2(u, nb);
}

// ---------------- SpMM helper: full-warp gather accumulate ----------------
__device__ __forceinline__ void addH(float& ax, float& ay, float n, __half2 h) {
    float2 f = __half22float2(h);
    ax = fmaf(n, f.x, ax);
    ay = fmaf(n, f.y, ay);
}

// ---------------- K6-8: SpMM, one warp per dest node, full-warp per edge ----------------
// lout < 3: write fp16 layer buffer. lout == 3: fuse final l2norm((x0+x1+x2+x3)/4) -> out.
__global__ void k_spmm(int lin, int lout, float* __restrict__ out) {
    int gw = (blockIdx.x * blockDim.x + threadIdx.x) >> 5;
    if (gw >= N) return;
    int l = threadIdx.x & 31;
    const __half2* __restrict__ xin = g_xl[lin];
    size_t idx = (size_t)gw * NH + l;

    int   beg = g_off[gw];
    int   end = beg + g_cnt[gw];
    float di  = g_dinv[gw];

    float2 s = __half22float2(xin[idx]);
    float ax = s.x * (di * di), ay = s.y * (di * di);   // self loop

    const int2* edges = (const int2*)g_edge4;
    int e = beg;
    if ((e & 1) && e < end) {                      // align to pair boundary
        int2 ed = edges[e];
        addH(ax, ay, __int_as_float(ed.y), xin[(size_t)ed.x * NH + l]);
        e++;
    }
    int pend = e + ((end - e) & ~1);               // pair-aligned end

    for (; e + 8 <= pend; e += 8) {                // 4 int4 loads = 8 edges, 8 gathers in flight
        int4 p0 = g_edge4[(e >> 1) + 0];
        int4 p1 = g_edge4[(e >> 1) + 1];
        int4 p2 = g_edge4[(e >> 1) + 2];
        int4 p3 = g_edge4[(e >> 1) + 3];
        __half2 v0 = xin[(size_t)p0.x * NH + l];
        __half2 v1 = xin[(size_t)p0.z * NH + l];
        __half2 v2 = xin[(size_t)p1.x * NH + l];
        __half2 v3 = xin[(size_t)p1.z * NH + l];
        __half2 v4 = xin[(size_t)p2.x * NH + l];
        __half2 v5 = xin[(size_t)p2.z * NH + l];
        __half2 v6 = xin[(size_t)p3.x * NH + l];
        __half2 v7 = xin[(size_t)p3.z * NH + l];
        addH(ax, ay, __int_as_float(p0.y), v0);
        addH(ax, ay, __int_as_float(p0.w), v1);
        addH(ax, ay, __int_as_float(p1.y), v2);
        addH(ax, ay, __int_as_float(p1.w), v3);
        addH(ax, ay, __int_as_float(p2.y), v4);
        addH(ax, ay, __int_as_float(p2.w), v5);
        addH(ax, ay, __int_as_float(p3.y), v6);
        addH(ax, ay, __int_as_float(p3.w), v7);
    }
    for (; e + 2 <= pend; e += 2) {
        int4 p = g_edge4[e >> 1];
        __half2 va = xin[(size_t)p.x * NH + l];
        __half2 vb = xin[(size_t)p.z * NH + l];
        addH(ax, ay, __int_as_float(p.y), va);
        addH(ax, ay, __int_as_float(p.w), vb);
    }
    if (pend < end) {                              // single trailing edge
        int2 ed = edges[pend];
        addH(ax, ay, __int_as_float(ed.y), xin[(size_t)ed.x * NH + l]);
    }

    if (lout < 3) {
        g_xl[lout][idx] = __floats2half2_rn(ax, ay);
    } else {
        // fused final: acc = x0 + x1 + x2 + x3(this); l2norm(acc/4)
        float2 a0 = __half22float2(g_xl[0][idx]);
        float2 a1 = __half22float2(g_xl[1][idx]);
        float2 a2 = __half22float2(g_xl[2][idx]);
        float fx = (ax + a0.x + a1.x + a2.x) * 0.25f;
        float fy = (ay + a0.y + a1.y + a2.y) * 0.25f;
        float ss = fx * fx + fy * fy;
        #pragma unroll
        for (int o = 16; o; o >>= 1) ss += __shfl_xor_sync(0xffffffffu, ss, o);
        float inv = 1.0f / fmaxf(sqrtf(ss), EPS);
        ((float2*)(out + (size_t)gw * D))[l] = make_float2(fx * inv, fy * inv);
    }
}

// ---------------- launcher ----------------
extern "C" void kernel_launch(void* const* d_in, const int* in_sizes, int n_in,
                              void* d_out, int out_size) {
    const float* user_w     = (const float*)d_in[0];
    const float* item_audio = (const float*)d_in[1];
    const float* artist_w   = (const float*)d_in[2];
    const float* album_w    = (const float*)d_in[3];
    const float* proj_W     = (const float*)d_in[4];
    const float* proj_b     = (const float*)d_in[5];
    const float* edge_w     = (const float*)d_in[6];
    const int*   u_idx      = (const int*)d_in[7];
    const int*   i_idx      = (const int*)d_in[8];
    const int*   artist_ids = (const int*)d_in[9];
    const int*   album_ids  = (const int*)d_in[10];
    float* out = (float*)d_out;

    const int TB = 256;
    int nz = (N + TB - 1) / TB;                 // zero blocks
    int gE = (E + TB - 1) / TB;

    // k_item dynamic smem: As + Bs + bias
    int smemItem = (TM * APAD + 128 * BPAD + 64) * (int)sizeof(float);
    cudaFuncSetAttribute(k_item, cudaFuncAttributeMaxDynamicSharedMemorySize, smemItem);

    k1_init_user<<<nz + (U + 7) / 8, TB>>>(user_w, nz);
    k_deg <<<gE, TB>>>(edge_w, u_idx, i_idx);
    k_item<<<(I + TM - 1) / TM, TB, smemItem>>>(item_audio, artist_w, album_w,
                                                proj_W, proj_b, artist_ids, album_ids);
    k_scan1<<<NBLK, 1024>>>();
    k_scan3<<<NBLK, 1024>>>();
    k_fill <<<gE, TB>>>(edge_w, u_idx, i_idx);

    int gW = (N * 32 + TB - 1) / TB;
    k_spmm <<<gW, TB>>>(0, 1, out);
    k_spmm <<<gW, TB>>>(1, 2, out);
    k_spmm <<<gW, TB>>>(2, 3, out);   // fused final layer + l2norm
}